// round 5
// baseline (speedup 1.0000x reference)
#include <cuda_runtime.h>
#include <cstdint>

#define BB 8
#define SS 8192
#define NTOK (BB * SS)

#define SLICES 16
#define SL_F4 8            // float4 lanes per 32-dim slice
#define TOK_BLK 1024       // tokens per embed block

typedef unsigned long long u64;

// Per-token packed word:
//   bits [0,48)  : addr one-hot (lo/hi/top nibbles)
//   bit 48: THINK_START(456)  bit 49: THINK_END(457)  bit 50: MEM_EXEC(458)
//   bits [52,61) : token id (0..271)
__device__ u64 g_mask[NTOK];

// ---------------------------------------------------------------------------
// Kernel 1: per-row scan + per-token mask computation (unchanged from R3/R4).
// ---------------------------------------------------------------------------
__global__ void __launch_bounds__(1024) nvm_scan_kernel(const int* __restrict__ tok) {
    __shared__ int sh[SS];
    __shared__ int warp_part[32];
    __shared__ int ce_sh;

    int b = blockIdx.x;
    int tid = threadIdx.x;
    int lane = tid & 31;
    int wid = tid >> 5;

    if (tid == 0) ce_sh = SS;

    const int4* row4 = reinterpret_cast<const int4*>(tok + b * SS);
    int4* sh4 = reinterpret_cast<int4*>(sh);
#pragma unroll
    for (int i = tid; i < SS / 4; i += 1024) sh4[i] = row4[i];
    __syncthreads();

    int base = tid * 8;

    int win[16];
    {
        int4 a, c;
        if (tid > 0) { a = sh4[tid * 2 - 2]; c = sh4[tid * 2 - 1]; }
        else { a = make_int4(0, 0, 0, 0); c = a; }
        win[0] = a.x; win[1] = a.y; win[2] = a.z; win[3] = a.w;
        win[4] = c.x; win[5] = c.y; win[6] = c.z; win[7] = c.w;
        int4 d = sh4[tid * 2];
        int4 e = sh4[tid * 2 + 1];
        win[8]  = d.x; win[9]  = d.y; win[10] = d.z; win[11] = d.w;
        win[12] = e.x; win[13] = e.y; win[14] = e.z; win[15] = e.w;
    }

    int vals[8];
    int run = -1, lce = SS;
#pragma unroll
    for (int i = 0; i < 8; i++) {
        int t = win[8 + i];
        if (t == 256) run = base + i;
        vals[i] = run;
        if (t == 257 && (base + i) < lce) lce = base + i;
    }
    if (lce < SS) atomicMin(&ce_sh, lce);

    int v = run;
#pragma unroll
    for (int off = 1; off < 32; off <<= 1) {
        int o = __shfl_up_sync(0xffffffffu, v, off);
        if (lane >= off && o > v) v = o;
    }
    if (lane == 31) warp_part[wid] = v;
    __syncthreads();
    if (wid == 0) {
        int w = warp_part[lane];
#pragma unroll
        for (int off = 1; off < 32; off <<= 1) {
            int o = __shfl_up_sync(0xffffffffu, w, off);
            if (lane >= off && o > w) w = o;
        }
        warp_part[lane] = w;
    }
    __syncthreads();

    int warp_prefix = (wid == 0) ? -1 : warp_part[wid - 1];
    int excl_in_warp = __shfl_up_sync(0xffffffffu, v, 1);
    if (lane == 0) excl_in_warp = -1;
    int prefix = (excl_in_warp > warp_prefix) ? excl_in_warp : warp_prefix;
    int fce = ce_sh;

    u64 out[8];
#pragma unroll
    for (int i = 0; i < 8; i++) {
        int s = base + i;
        int t = win[8 + i];
        int cs = (vals[i] > prefix) ? vals[i] : prefix;

        u64 m = ((u64)t) << 52;
        if (t == 259) m |= (1ull << 48);
        if (t == 260) m |= (1ull << 49);
        if (t == 258 && (s + 8) < SS) m |= (1ull << 50);

        if (cs >= 0 && s < fce && t < 256) {
            int seq = s - cs - 1;
            int bo  = seq & 7;
            if (seq >= 0 && bo < 5) {
                int addr = (((seq >> 3) << 3) + 2 + bo) & 4095;
                m |= (1ull << (addr & 15))
                   | (1ull << (16 + ((addr >> 4) & 15)))
                   | (1ull << (32 + ((addr >> 8) & 15)));
            }
        }
#pragma unroll
        for (int off = 0; off < 4; off++) {
            int jg = s - 5 - off;
            int ji = i + 3 - off;
            if (jg >= 0 && (jg + 8) < SS && win[ji] == 258) {
                int a = ((win[ji + 1] | (win[ji + 2] << 8)) + off) & 4095;
                m |= (1ull << (a & 15))
                   | (1ull << (16 + ((a >> 4) & 15)))
                   | (1ull << (32 + ((a >> 8) & 15)));
            }
        }
        out[i] = m;
    }

    ulonglong2* gm2 = reinterpret_cast<ulonglong2*>(&g_mask[b * SS + base]);
#pragma unroll
    for (int k = 0; k < 4; k++)
        gm2[k] = make_ulonglong2(out[2 * k], out[2 * k + 1]);
}

// ---------------------------------------------------------------------------
// Kernel 2: dim-sliced embed. blockIdx.y = 32-dim slice, blockIdx.x = token
// chunk of 1024. Table slice (34 KB) + masks (8 KB) staged in SMEM; inner
// loop is LDS -> (optional mask) -> STG.128. No L2 on the gather path.
// ---------------------------------------------------------------------------
__device__ __forceinline__ void apply_mask(float4& v, u64 m, int glane) {
    if (glane >= 51 && glane <= 63) {
        int d0 = glane << 2;
        float* vp = reinterpret_cast<float*>(&v);
#pragma unroll
        for (int c = 0; c < 4; c++) {
            int d = d0 + c;
            if (d >= 206 && d < 254 && ((m >> (d - 206)) & 1ull)) vp[c] = 1.0f;
        }
    } else if (glane == 114) {
        if ((m >> 48) & 1ull) v.x = 1.0f;   // 456
        if ((m >> 49) & 1ull) v.y = 1.0f;   // 457
        if ((m >> 50) & 1ull) v.z = 1.0f;   // 458
    }
}

__global__ void __launch_bounds__(256) nvm_embed_kernel(
    const float4* __restrict__ tbl4,          // [272 * 128]
    float4* __restrict__ out4)                // [NTOK * 128]
{
    __shared__ float4 stbl[272 * SL_F4];      // 34 KB table slice
    __shared__ u64 smask[TOK_BLK];            // 8 KB masks

    int sl = blockIdx.y;                      // 0..15
    int tokbase = blockIdx.x * TOK_BLK;
    int tid = threadIdx.x;

    // stage masks (coalesced 16B)
    {
        ulonglong2* sm2 = reinterpret_cast<ulonglong2*>(smask);
        const ulonglong2* gm2 =
            reinterpret_cast<const ulonglong2*>(&g_mask[tokbase]);
#pragma unroll
        for (int i = tid; i < TOK_BLK / 2; i += 256) sm2[i] = gm2[i];
    }
    // stage table slice: 272 rows x 8 float4
#pragma unroll
    for (int i = tid; i < 272 * SL_F4; i += 256) {
        int r = i >> 3, l = i & 7;
        stbl[i] = __ldg(&tbl4[r * 128 + sl * SL_F4 + l]);
    }
    __syncthreads();

    int l = tid & 7;                 // lane within slice
    int g = tid >> 3;                // token group 0..31
    int glane = sl * SL_F4 + l;      // global float4 lane
    bool needmask = (sl == 6) | (sl == 7) | (sl == 14);

    float4* outp = out4 + (size_t)tokbase * 128 + glane;

    if (needmask) {
#pragma unroll 4
        for (int k = 0; k < 32; k++) {
            int t = g + 32 * k;
            u64 m = smask[t];
            int id = (int)((m >> 52) & 511);
            float4 v = stbl[id * SL_F4 + l];
            apply_mask(v, m, glane);
            __stcs(outp + (size_t)t * 128, v);
        }
    } else {
#pragma unroll 4
        for (int k = 0; k < 32; k++) {
            int t = g + 32 * k;
            u64 m = smask[t];
            int id = (int)((m >> 52) & 511);
            float4 v = stbl[id * SL_F4 + l];
            __stcs(outp + (size_t)t * 128, v);
        }
    }
}

// ---------------------------------------------------------------------------
extern "C" void kernel_launch(void* const* d_in, const int* in_sizes, int n_in,
                              void* d_out, int out_size) {
    const float* tbl;
    const int* tok;
    if (in_sizes[0] == 272 * 512) {
        tbl = (const float*)d_in[0];
        tok = (const int*)d_in[1];
    } else {
        tbl = (const float*)d_in[1];
        tok = (const int*)d_in[0];
    }
    float* out = (float*)d_out;

    nvm_scan_kernel<<<BB, 1024>>>(tok);

    dim3 grid(NTOK / TOK_BLK, SLICES);   // (64, 16)
    nvm_embed_kernel<<<grid, 256>>>((const float4*)tbl, (float4*)out);
}